// round 3
// baseline (speedup 1.0000x reference)
#include <cuda_runtime.h>

#define Bsz   128
#define Tt    512
#define INs   27
#define Hh    256
#define G4    1024
#define NB    128
#define OUTs  128

// ---- persistent device scratch (static: no runtime allocation) ----
__device__ float g_G[(size_t)Tt * G4 * Bsz];   // [t][g(1024)][b]
__device__ float g_h[2][Hh * Bsz];             // [k][b], double buffered
__device__ __align__(128) int g_flags[4][32];  // per-group publish counters (1 line/group)

// ---------------- helpers ----------------
__device__ __forceinline__ void fma2(unsigned long long& d, unsigned long long a, unsigned long long b) {
    asm("fma.rn.f32x2 %0, %1, %2, %0;" : "+l"(d) : "l"(a), "l"(b));
}
__device__ __forceinline__ float f2lo(unsigned long long u) { return __uint_as_float((unsigned)u); }
__device__ __forceinline__ float f2hi(unsigned long long u) { return __uint_as_float((unsigned)(u >> 32)); }

__device__ __forceinline__ float sigf(float x) {
    return __fdividef(1.f, 1.f + __expf(-x));
}
__device__ __forceinline__ float tanhf_(float x) {
    float e = __expf(-2.f * fabsf(x));
    float r = __fdividef(1.f - e, 1.f + e);
    return copysignf(r, x);
}

// ---------------- kernels ----------------
// G[t][g][b] = b_ih[g] + b_hh[g] + sum_{k<27} x[b][t][k] * W_ih[g][k]
// Also: zero g_h[0] (spread over the 512 t-blocks of gc==0),
//       set ALL 128 flags to 1 ("h_0 published") from the (t==0,gc==0) block.
__global__ void pre_kernel(const float* __restrict__ x,
                           const float* __restrict__ W_ih,
                           const float* __restrict__ b_ih,
                           const float* __restrict__ b_hh) {
    __shared__ float xs[Bsz * INs];
    const int t   = blockIdx.x;
    const int gc  = blockIdx.y;       // 0..7, 128 gates each
    const int tid = threadIdx.x;      // = b  (blockDim.x == 128)

    if (gc == 0) {
        if (tid < 64) g_h[0][t * 64 + tid] = 0.f;            // 512 blocks x 64 = 32768
        if (t == 0) ((int*)g_flags)[tid] = 1;                // all 128 flags
    }

    for (int i = tid; i < Bsz * INs; i += 128) {
        int b = i / INs, k = i - b * INs;
        xs[i] = x[((size_t)b * Tt + t) * INs + k];
    }
    __syncthreads();
    float xr[INs];
    #pragma unroll
    for (int k = 0; k < INs; ++k) xr[k] = xs[tid * INs + k];

    for (int g0 = 0; g0 < 128; ++g0) {
        int g = (gc << 7) + g0;
        float acc = b_ih[g] + b_hh[g];
        const float* wr = W_ih + g * 47;   // NN_IN = 47, only first 27 cols used
        #pragma unroll
        for (int k = 0; k < INs; ++k) acc += xr[k] * __ldg(wr + k);
        g_G[((size_t)t * G4 + g) * Bsz + tid] = acc;
    }
}

// Persistent sequential LSTM. grid = 128 blocks = 4 b-groups(32 batches) x 32 j-tiles(8).
// Groups are fully independent: sync is 32 per-producer flags per group.
__global__ void __launch_bounds__(256, 1)
step_kernel(const float* __restrict__ W_hh,
            const float* __restrict__ W_fc,
            const float* __restrict__ b_fc,
            float* __restrict__ out) {
    extern __shared__ float sm[];
    float* sW = sm;                          // 16384 floats
    float* sH = sm + 256 * 64;               //  8192 floats
    float* sR = sm + 256 * 64 + 256 * 32;    //  4608 floats

    const int tid = threadIdx.x;
    const int g   = blockIdx.x >> 5;         // b-group 0..3
    const int jt  = blockIdx.x & 31;         // j-tile 0..31
    const int b0  = g << 5;
    const int j0  = jt << 3;

    // ---- load W_hh tile once, duplicated into f32x2 pairs ----
    for (int i = tid; i < 256 * 32; i += 256) {
        int k = i >> 5, r = i & 31;          // r = jl*4 + gate
        int jl = r >> 2, gg = r & 3;
        float w = W_hh[(((gg << 8) + j0 + jl) << 8) + k];
        sW[(k << 6) + (r << 1)]     = w;
        sW[(k << 6) + (r << 1) + 1] = w;
    }

    // compute-role mapping: 4 k-splits x (8 b-quads x 8 j)
    const int ks   = tid >> 6;
    const int pos  = tid & 63;
    const int bq   = pos & 7;
    const int jl   = pos >> 3;
    const int hoff = bq << 2;
    const int woff = jl << 3;
    const int kb   = ks << 6;

    // epilogue-role mapping: 256 threads = 64 pos x 4 b-sub
    const int pe = tid >> 2;
    const int bi = tid & 3;
    const int je = j0 + (pe >> 3);
    const int be = b0 + ((pe & 7) << 2) + bi;

    const int* myflags = g_flags[g];
    float cold = 0.f;                        // c lives in a register for all 512 steps

    for (int s = 0; s < Tt; ++s) {
        const float* hin  = g_h[s & 1];
        float*       hout = g_h[(s + 1) & 1];

        // ---- wait for h_s from all 32 producers of this group ----
        if (tid < 32) {
            const int* fp = myflags + tid;
            int v;
            do {
                asm volatile("ld.acquire.gpu.s32 %0, [%1];" : "=r"(v) : "l"(fp) : "memory");
            } while (v < s + 1);
        }
        __syncthreads();

        // prefetch G (DRAM) — latency hidden behind staging + GEMM
        float gp0 = g_G[(((size_t)s * 4 + 0) * 256 + je) * Bsz + be];
        float gp1 = g_G[(((size_t)s * 4 + 1) * 256 + je) * Bsz + be];
        float gp2 = g_G[(((size_t)s * 4 + 2) * 256 + je) * Bsz + be];
        float gp3 = g_G[(((size_t)s * 4 + 3) * 256 + je) * Bsz + be];

        // stage h tile: sH[k][bl] = hin[k*128 + b0 + bl]  (float4)
        {
            const float4* src = (const float4*)hin;
            float4*       dst = (float4*)sH;
            #pragma unroll
            for (int i4 = tid; i4 < 2048; i4 += 256) {
                int k = i4 >> 3, q = i4 & 7;
                dst[i4] = src[(k << 5) + (b0 >> 2) + q];
            }
        }
        __syncthreads();

        // ---- packed f32x2 GEMM: 4b x 8 gate-rows over 64 k ----
        unsigned long long acc[8];
        #pragma unroll
        for (int a = 0; a < 8; ++a) acc[a] = 0ULL;

        #pragma unroll 8
        for (int kk = 0; kk < 64; ++kk) {
            int k = kb + kk;
            ulonglong2 hv = *(const ulonglong2*)(sH + (k << 5) + hoff);
            ulonglong2 wA = *(const ulonglong2*)(sW + (k << 6) + woff);
            ulonglong2 wB = *(const ulonglong2*)(sW + (k << 6) + woff + 4);
            fma2(acc[0], hv.x, wA.x); fma2(acc[1], hv.y, wA.x);
            fma2(acc[2], hv.x, wA.y); fma2(acc[3], hv.y, wA.y);
            fma2(acc[4], hv.x, wB.x); fma2(acc[5], hv.y, wB.x);
            fma2(acc[6], hv.x, wB.y); fma2(acc[7], hv.y, wB.y);
        }

        // ---- k-split reduction via padded shared (stride 72: conflict-free) ----
        #pragma unroll
        for (int gg = 0; gg < 4; ++gg) {
            unsigned long long A0 = acc[gg * 2], A1 = acc[gg * 2 + 1];
            int base = ((ks << 4) + (gg << 2)) * 72 + pos;
            sR[base]       = f2lo(A0);
            sR[base + 72]  = f2hi(A0);
            sR[base + 144] = f2lo(A1);
            sR[base + 216] = f2hi(A1);
        }
        __syncthreads();

        // ---- epilogue: sum splits, add G, LSTM cell update ----
        {
            float v0 = gp0, v1 = gp1, v2 = gp2, v3 = gp3;
            #pragma unroll
            for (int kss = 0; kss < 4; ++kss) {
                int base = ((kss << 4) + bi) * 72 + pe;
                v0 += sR[base];
                v1 += sR[base + 4 * 72];
                v2 += sR[base + 8 * 72];
                v3 += sR[base + 12 * 72];
            }
            float ig = sigf(v0), fg = sigf(v1);
            float gg = tanhf_(v2), og = sigf(v3);
            float cn = fg * cold + ig * gg;
            float hn = og * tanhf_(cn);
            cold = cn;
            hout[(je << 7) + be] = hn;
        }
        __syncthreads();     // all hn stores done before publishing

        // ---- publish h_{s+1}: release-store monotonic counter ----
        if (tid == 0) {
            asm volatile("st.release.gpu.s32 [%0], %1;"
                         :: "l"(&g_flags[g][jt]), "r"(s + 2) : "memory");
        }
    }

    // ---- wait for final h from whole group, then classifier head ----
    if (tid < 32) {
        const int* fp = myflags + tid;
        int v;
        do {
            asm volatile("ld.acquire.gpu.s32 %0, [%1];" : "=r"(v) : "l"(fp) : "memory");
        } while (v < Tt + 1);
    }
    __syncthreads();

    {
        const float* hf = g_h[0];            // final h lives in buffer 0 (T even)
        const int bb = b0 + jt;              // this block's batch (within its group)
        if (tid < OUTs) {
            float acc = b_fc[tid];
            const float* wr = W_fc + tid * Hh;
            #pragma unroll 8
            for (int k = 0; k < Hh; ++k)
                acc += hf[(k << 7) + bb] * wr[k];
            out[bb * OUTs + tid] = acc;
        }
    }
}

// ---------------- launcher ----------------
extern "C" void kernel_launch(void* const* d_in, const int* in_sizes, int n_in,
                              void* d_out, int out_size) {
    const float* x    = (const float*)d_in[0];
    // d_in[1] = input_lengths (unused by the reference)
    const float* W_ih = (const float*)d_in[2];
    const float* W_hh = (const float*)d_in[3];
    const float* b_ih = (const float*)d_in[4];
    const float* b_hh = (const float*)d_in[5];
    // d_in[6], d_in[7] = W_xi, b_xi — dead code (memory never affects output)
    const float* W_fc = (const float*)d_in[8];
    const float* b_fc = (const float*)d_in[9];
    float* out = (float*)d_out;

    cudaFuncSetAttribute(step_kernel, cudaFuncAttributeMaxDynamicSharedMemorySize, 116736);

    pre_kernel<<<dim3(Tt, 8), 128>>>(x, W_ih, b_ih, b_hh);
    step_kernel<<<NB, 256, 116736>>>(W_hh, W_fc, b_fc, out);
}

// round 4
// speedup vs baseline: 1.2648x; 1.2648x over previous
#include <cuda_runtime.h>

#define Bsz   128
#define Tt    512
#define INs   27
#define Hh    256
#define G4    1024
#define NB    128
#define OUTs  128

// ---- persistent device scratch (static: no runtime allocation) ----
__device__ float g_G[(size_t)Tt * G4 * Bsz];   // [t][g(1024)][b]
__device__ float g_h[2][Hh * Bsz];             // [k][b], double buffered
// per-group barrier state: one 128B line per group, monotonic across replays
__device__ __align__(128) unsigned long long g_cnt[64];   // group g at [g*16]
__device__ __align__(128) unsigned long long g_rel[64];

// ---------------- helpers ----------------
__device__ __forceinline__ void fma2(unsigned long long& d, unsigned long long a, unsigned long long b) {
    asm("fma.rn.f32x2 %0, %1, %2, %0;" : "+l"(d) : "l"(a), "l"(b));
}
__device__ __forceinline__ float sigf(float x) {
    return __fdividef(1.f, 1.f + __expf(-x));
}
__device__ __forceinline__ float tanhf_(float x) {
    float e = __expf(-2.f * fabsf(x));
    float r = __fdividef(1.f - e, 1.f + e);
    return copysignf(r, x);
}

// per-group barrier: 32 arrivals on g_cnt[g], release via g_rel[g]
__device__ __forceinline__ void group_bar(int g) {
    __syncthreads();
    if (threadIdx.x == 0) {
        unsigned long long* cnt = &g_cnt[g * 16];
        unsigned long long* rel = &g_rel[g * 16];
        unsigned long long old, one = 1ULL;
        asm volatile("atom.acq_rel.gpu.add.u64 %0, [%1], %2;"
                     : "=l"(old) : "l"(cnt), "l"(one) : "memory");
        unsigned long long gen = old >> 5;                 // / 32 blocks per group
        if ((old & 31ULL) == 31ULL) {
            asm volatile("red.release.gpu.add.u64 [%0], %1;"
                         :: "l"(rel), "l"(one) : "memory");
        } else {
            unsigned long long cur;
            do {
                asm volatile("ld.acquire.gpu.u64 %0, [%1];"
                             : "=l"(cur) : "l"(rel) : "memory");
            } while (cur <= gen);
        }
    }
    __syncthreads();
}

// ---------------- kernels ----------------
// G[t][g][b] = b_ih[g] + b_hh[g] + sum_{k<27} x[b][t][k] * W_ih[g][k]
// Also zero g_h[0] (h_0) spread over the gc==0 blocks.
__global__ void pre_kernel(const float* __restrict__ x,
                           const float* __restrict__ W_ih,
                           const float* __restrict__ b_ih,
                           const float* __restrict__ b_hh) {
    __shared__ float xs[Bsz * INs];
    const int t   = blockIdx.x;
    const int gc  = blockIdx.y;       // 0..7, 128 gates each
    const int tid = threadIdx.x;      // = b  (blockDim.x == 128)

    if (gc == 0 && tid < 64) g_h[0][t * 64 + tid] = 0.f;   // 512 blocks x 64 = 32768

    for (int i = tid; i < Bsz * INs; i += 128) {
        int b = i / INs, k = i - b * INs;
        xs[i] = x[((size_t)b * Tt + t) * INs + k];
    }
    __syncthreads();
    float xr[INs];
    #pragma unroll
    for (int k = 0; k < INs; ++k) xr[k] = xs[tid * INs + k];

    for (int g0 = 0; g0 < 128; ++g0) {
        int g = (gc << 7) + g0;
        float acc = b_ih[g] + b_hh[g];
        const float* wr = W_ih + g * 47;   // NN_IN = 47, only first 27 cols used
        #pragma unroll
        for (int k = 0; k < INs; ++k) acc += xr[k] * __ldg(wr + k);
        g_G[((size_t)t * G4 + g) * Bsz + tid] = acc;
    }
}

// Persistent sequential LSTM. grid = 128 blocks = 4 b-groups(32 batches) x 32 j-tiles(8 j).
// W_hh tile lives in REGISTERS (step-invariant); h reads are warp-broadcast LDS.
// Warp roles: lane = gate-row (32 rows = 8 j x 4 gates); warp = (pairset pw in {0,1}) x (ksplit ks in 0..3).
__global__ void __launch_bounds__(256, 1)
step_kernel(const float* __restrict__ W_hh,
            const float* __restrict__ W_fc,
            const float* __restrict__ b_fc,
            float* __restrict__ out) {
    extern __shared__ float sm[];
    float*              sH  = sm;                                  // 8192 floats (32KB): [k][32 b]
    unsigned long long* sRd = (unsigned long long*)(sm + 8192);    // 2176 x 8B (padded stride 17)
    float*              sRf = (float*)sRd;

    const int tid  = threadIdx.x;
    const int warp = tid >> 5;
    const int lane = tid & 31;
    const int g    = blockIdx.x >> 5;         // b-group 0..3
    const int jt   = blockIdx.x & 31;         // j-tile 0..31
    const int b0   = g << 5;
    const int j0   = jt << 3;

    const int pw = warp & 1;                  // batch pairset: pairs [8pw, 8pw+8)
    const int ks = warp >> 1;                 // k-split: k in [64ks, 64ks+64)
    const int kb = ks << 6;

    // this lane's gate-row: row = jl*4 + gate
    const int jl_r   = lane >> 2;
    const int gate_r = lane & 3;
    const int row_g  = (gate_r << 8) + j0 + jl_r;    // W_hh row (gate*256 + j)

    // ---- W slice in registers for the whole kernel ----
    float w[64];
    {
        const float* wp = W_hh + ((size_t)row_g << 8) + kb;
        #pragma unroll
        for (int kk = 0; kk < 64; ++kk) w[kk] = wp[kk];
    }

    // epilogue mapping: warp = jl (0..7), lane = batch b (0..31)
    const int ej = warp;
    const int eb = lane;
    const int je = j0 + ej;
    const int be = b0 + eb;

    float cold = 0.f;                          // c stays in a register for all steps

    for (int s = 0; s < Tt; ++s) {
        const float* hin  = g_h[s & 1];
        float*       hout = g_h[(s + 1) & 1];

        // prefetch G (independent of h_s) BEFORE the barrier — DRAM latency hides in the wait
        size_t gb = ((size_t)s << 10) + j0 + ej;                 // s*1024 + j
        float gp0 = g_G[(gb        ) * Bsz + be];
        float gp1 = g_G[(gb +  256 ) * Bsz + be];
        float gp2 = g_G[(gb +  512 ) * Bsz + be];
        float gp3 = g_G[(gb +  768 ) * Bsz + be];

        // ---- group barrier: all 32 producers of this group published h_s ----
        group_bar(g);

        // stage h tile: sH[k][bl] = hin[k*128 + b0 + bl]  (float4)
        {
            const float4* src = (const float4*)hin;
            float4*       dst = (float4*)sH;
            #pragma unroll
            for (int i4 = tid; i4 < 2048; i4 += 256) {
                int k = i4 >> 3, q = i4 & 7;
                dst[i4] = src[(k << 5) + (b0 >> 2) + q];
            }
        }
        __syncthreads();

        // ---- GEMM: W in regs, h via broadcast LDS; 8 pairs x 64 k per lane ----
        unsigned long long acc[8];
        #pragma unroll
        for (int a = 0; a < 8; ++a) acc[a] = 0ULL;

        #pragma unroll
        for (int kk = 0; kk < 64; ++kk) {
            const ulonglong2* hp = (const ulonglong2*)(sH + ((kb + kk) << 5) + (pw << 4));
            ulonglong2 hA = hp[0];             // pairs 0,1 (broadcast: all lanes same addr)
            ulonglong2 hB = hp[1];             // pairs 2,3
            ulonglong2 hC = hp[2];             // pairs 4,5
            ulonglong2 hD = hp[3];             // pairs 6,7
            unsigned long long wd;
            asm("mov.b64 %0, {%1, %1};" : "=l"(wd) : "f"(w[kk]));
            fma2(acc[0], hA.x, wd); fma2(acc[1], hA.y, wd);
            fma2(acc[2], hB.x, wd); fma2(acc[3], hB.y, wd);
            fma2(acc[4], hC.x, wd); fma2(acc[5], hC.y, wd);
            fma2(acc[6], hD.x, wd); fma2(acc[7], hD.y, wd);
        }

        // ---- k-split partials to padded shared: [(ks*32+row)*17 + pair] (f32x2) ----
        {
            int base = ((ks << 5) + lane) * 17 + (pw << 3);
            #pragma unroll
            for (int p = 0; p < 8; ++p) sRd[base + p] = acc[p];
        }
        __syncthreads();

        // ---- epilogue: sum 4 splits, add G, LSTM cell update ----
        {
            float v0 = gp0, v1 = gp1, v2 = gp2, v3 = gp3;
            #pragma unroll
            for (int kss = 0; kss < 4; ++kss) {
                int rbase = (kss << 5) + (ej << 2);
                v0 += sRf[(rbase + 0) * 34 + eb];
                v1 += sRf[(rbase + 1) * 34 + eb];
                v2 += sRf[(rbase + 2) * 34 + eb];
                v3 += sRf[(rbase + 3) * 34 + eb];
            }
            float ig = sigf(v0), fg = sigf(v1);
            float gg = tanhf_(v2), og = sigf(v3);
            float cn = fg * cold + ig * gg;
            float hn = og * tanhf_(cn);
            cold = cn;
            hout[(je << 7) + be] = hn;
        }
        __syncthreads();     // all hn stores issued before next arrival
    }

    // ---- final group barrier (h_T visible), then classifier head ----
    group_bar(g);
    {
        const float* hf = g_h[0];            // final h lives in buffer 0 (T even)
        const int bb = b0 + jt;              // this block's batch
        if (tid < OUTs) {
            float acc = b_fc[tid];
            const float* wr = W_fc + tid * Hh;
            #pragma unroll 8
            for (int k = 0; k < Hh; ++k)
                acc += hf[(k << 7) + bb] * wr[k];
            out[bb * OUTs + tid] = acc;
        }
    }
}

// ---------------- launcher ----------------
extern "C" void kernel_launch(void* const* d_in, const int* in_sizes, int n_in,
                              void* d_out, int out_size) {
    const float* x    = (const float*)d_in[0];
    // d_in[1] = input_lengths (unused by the reference)
    const float* W_ih = (const float*)d_in[2];
    const float* W_hh = (const float*)d_in[3];
    const float* b_ih = (const float*)d_in[4];
    const float* b_hh = (const float*)d_in[5];
    // d_in[6], d_in[7] = W_xi, b_xi — dead code (memory never affects output)
    const float* W_fc = (const float*)d_in[8];
    const float* b_fc = (const float*)d_in[9];
    float* out = (float*)d_out;

    // smem: 32768 (sH) + 17408 (sR padded) = 50176 bytes
    cudaFuncSetAttribute(step_kernel, cudaFuncAttributeMaxDynamicSharedMemorySize, 50176);

    pre_kernel<<<dim3(Tt, 8), 128>>>(x, W_ih, b_ih, b_hh);
    step_kernel<<<NB, 256, 50176>>>(W_hh, W_fc, b_fc, out);
}

// round 5
// speedup vs baseline: 1.3147x; 1.0395x over previous
#include <cuda_runtime.h>

#define Bsz   128
#define Tt    512
#define INs   27
#define Hh    256
#define G4    1024
#define NB    128
#define OUTs  128

// ---- persistent device scratch (static: no runtime allocation) ----
__device__ float g_G[(size_t)Tt * G4 * Bsz];   // [t][g(1024)][b]
__device__ float g_h[2][Hh * Bsz];             // [k][b], double buffered
// per-group barrier state: one 128B line per group, monotonic across replays
__device__ __align__(128) unsigned long long g_cnt[64];   // group g at [g*16]
__device__ __align__(128) unsigned long long g_rel[64];

// ---------------- helpers ----------------
__device__ __forceinline__ void fma2(unsigned long long& d, unsigned long long a, unsigned long long b) {
    asm("fma.rn.f32x2 %0, %1, %2, %0;" : "+l"(d) : "l"(a), "l"(b));
}
__device__ __forceinline__ float sigf(float x) {
    return __fdividef(1.f, 1.f + __expf(-x));
}
__device__ __forceinline__ float tanhf_(float x) {
    float e = __expf(-2.f * fabsf(x));
    float r = __fdividef(1.f - e, 1.f + e);
    return copysignf(r, x);
}

// per-group barrier: 32 arrivals on g_cnt[g], release via g_rel[g]
__device__ __forceinline__ void group_bar(int g) {
    __syncthreads();
    if (threadIdx.x == 0) {
        unsigned long long* cnt = &g_cnt[g * 16];
        unsigned long long* rel = &g_rel[g * 16];
        unsigned long long old, one = 1ULL;
        asm volatile("atom.acq_rel.gpu.add.u64 %0, [%1], %2;"
                     : "=l"(old) : "l"(cnt), "l"(one) : "memory");
        unsigned long long gen = old >> 5;                 // / 32 blocks per group
        if ((old & 31ULL) == 31ULL) {
            asm volatile("red.release.gpu.add.u64 [%0], %1;"
                         :: "l"(rel), "l"(one) : "memory");
        } else {
            unsigned long long cur;
            do {
                asm volatile("ld.acquire.gpu.u64 %0, [%1];"
                             : "=l"(cur) : "l"(rel) : "memory");
            } while (cur <= gen);
        }
    }
    __syncthreads();
}

// ---------------- kernels ----------------
// G[t][g][b] = b_ih[g] + b_hh[g] + sum_{k<27} x[b][t][k] * W_ih[g][k]
// Also zero g_h[0] (h_0) spread over the gc==0 blocks.
__global__ void pre_kernel(const float* __restrict__ x,
                           const float* __restrict__ W_ih,
                           const float* __restrict__ b_ih,
                           const float* __restrict__ b_hh) {
    __shared__ float xs[Bsz * INs];
    const int t   = blockIdx.x;
    const int gc  = blockIdx.y;       // 0..7, 128 gates each
    const int tid = threadIdx.x;      // = b  (blockDim.x == 128)

    if (gc == 0 && tid < 64) g_h[0][t * 64 + tid] = 0.f;   // 512 blocks x 64 = 32768

    for (int i = tid; i < Bsz * INs; i += 128) {
        int b = i / INs, k = i - b * INs;
        xs[i] = x[((size_t)b * Tt + t) * INs + k];
    }
    __syncthreads();
    float xr[INs];
    #pragma unroll
    for (int k = 0; k < INs; ++k) xr[k] = xs[tid * INs + k];

    for (int g0 = 0; g0 < 128; ++g0) {
        int g = (gc << 7) + g0;
        float acc = b_ih[g] + b_hh[g];
        const float* wr = W_ih + g * 47;   // NN_IN = 47, only first 27 cols used
        #pragma unroll
        for (int k = 0; k < INs; ++k) acc += xr[k] * __ldg(wr + k);
        g_G[((size_t)t * G4 + g) * Bsz + tid] = acc;
    }
}

// Persistent sequential LSTM. grid = 128 blocks = 4 b-groups(32 batches) x 32 j-tiles(8 j).
// 512 threads = 16 warps: warp = (ks in 0..7: 32-k split) x (pw in 0..1: 8-pair set);
// lane = gate-row (8 j x 4 gates). W slice (32 floats) in registers for all steps.
__global__ void __launch_bounds__(512, 1)
step_kernel(const float* __restrict__ W_hh,
            const float* __restrict__ W_fc,
            const float* __restrict__ b_fc,
            float* __restrict__ out) {
    extern __shared__ float sm[];
    float*              sH  = sm;                                  // 8192 floats (32KB): [k][32 b]
    unsigned long long* sRd = (unsigned long long*)(sm + 8192);    // 256 rows x 17 u64 (padded)
    float*              sRf = (float*)sRd;

    const int tid  = threadIdx.x;
    const int warp = tid >> 5;
    const int lane = tid & 31;
    const int g    = blockIdx.x >> 5;         // b-group 0..3
    const int jt   = blockIdx.x & 31;         // j-tile 0..31
    const int b0   = g << 5;
    const int j0   = jt << 3;

    const int pw = warp & 1;                  // batch pairset: pairs [8pw, 8pw+8)
    const int ks = warp >> 1;                 // k-split: k in [32ks, 32ks+32)
    const int kb = ks << 5;

    // this lane's gate-row: row = jl*4 + gate
    const int jl_r   = lane >> 2;
    const int gate_r = lane & 3;
    const int row_g  = (gate_r << 8) + j0 + jl_r;    // W_hh row (gate*256 + j)

    // ---- W slice (32 k) in registers for the whole kernel ----
    float w[32];
    {
        const float* wp = W_hh + ((size_t)row_g << 8) + kb;
        #pragma unroll
        for (int kk = 0; kk < 32; ++kk) w[kk] = wp[kk];
    }

    // epilogue mapping (first 256 threads): ej = j-local, eb = batch-local
    const int ej = (tid >> 5) & 7;
    const int eb = lane;
    const int je = j0 + ej;
    const int be = b0 + eb;
    const bool epi = (tid < 256);

    float cold = 0.f;                          // c stays in a register for all steps

    for (int s = 0; s < Tt; ++s) {
        const float* hin  = g_h[s & 1];
        float*       hout = g_h[(s + 1) & 1];

        // prefetch G (independent of h_s) BEFORE the barrier — DRAM latency hides in the wait
        float gp0 = 0.f, gp1 = 0.f, gp2 = 0.f, gp3 = 0.f;
        if (epi) {
            size_t gb = ((size_t)s << 10) + j0 + ej;             // s*1024 + j
            gp0 = g_G[(gb        ) * Bsz + be];
            gp1 = g_G[(gb +  256 ) * Bsz + be];
            gp2 = g_G[(gb +  512 ) * Bsz + be];
            gp3 = g_G[(gb +  768 ) * Bsz + be];
        }

        // ---- group barrier: all 32 producers of this group published h_s ----
        group_bar(g);

        // stage h tile: sH[k][bl] = hin[k*128 + b0 + bl]  (float4, 4 per thread)
        {
            const float4* src = (const float4*)hin;
            float4*       dst = (float4*)sH;
            #pragma unroll
            for (int i4 = tid; i4 < 2048; i4 += 512) {
                int k = i4 >> 3, q = i4 & 7;
                dst[i4] = src[(k << 5) + (b0 >> 2) + q];
            }
        }
        __syncthreads();

        // ---- GEMM: W in regs, h via broadcast LDS; 8 pairs x 32 k per lane ----
        unsigned long long acc[8];
        #pragma unroll
        for (int a = 0; a < 8; ++a) acc[a] = 0ULL;

        #pragma unroll
        for (int kk = 0; kk < 32; ++kk) {
            const ulonglong2* hp = (const ulonglong2*)(sH + ((kb + kk) << 5) + (pw << 4));
            ulonglong2 hA = hp[0];             // pairs 0,1 (broadcast)
            ulonglong2 hB = hp[1];             // pairs 2,3
            ulonglong2 hC = hp[2];             // pairs 4,5
            ulonglong2 hD = hp[3];             // pairs 6,7
            unsigned long long wd;
            asm("mov.b64 %0, {%1, %1};" : "=l"(wd) : "f"(w[kk]));
            fma2(acc[0], hA.x, wd); fma2(acc[1], hA.y, wd);
            fma2(acc[2], hB.x, wd); fma2(acc[3], hB.y, wd);
            fma2(acc[4], hC.x, wd); fma2(acc[5], hC.y, wd);
            fma2(acc[6], hD.x, wd); fma2(acc[7], hD.y, wd);
        }

        // ---- partials to padded shared: row = (ks*32 + gate-row), 16 pairs + pad ----
        {
            int base = ((ks << 5) + lane) * 17 + (pw << 3);
            #pragma unroll
            for (int p = 0; p < 8; ++p) sRd[base + p] = acc[p];
        }
        __syncthreads();

        // ---- epilogue: sum 8 k-splits, add G, LSTM cell update (tid < 256) ----
        if (epi) {
            float v0 = gp0, v1 = gp1, v2 = gp2, v3 = gp3;
            #pragma unroll
            for (int kss = 0; kss < 8; ++kss) {
                int rbase = (kss << 5) + (ej << 2);
                v0 += sRf[(rbase + 0) * 34 + eb];
                v1 += sRf[(rbase + 1) * 34 + eb];
                v2 += sRf[(rbase + 2) * 34 + eb];
                v3 += sRf[(rbase + 3) * 34 + eb];
            }
            float ig = sigf(v0), fg = sigf(v1);
            float gg = tanhf_(v2), og = sigf(v3);
            float cn = fg * cold + ig * gg;
            float hn = og * tanhf_(cn);
            cold = cn;
            hout[(je << 7) + be] = hn;
        }
        __syncthreads();     // all hn stores issued before next arrival
    }

    // ---- final group barrier (h_T visible), then classifier head ----
    group_bar(g);
    {
        const float* hf = g_h[0];            // final h lives in buffer 0 (T even)
        const int bb = b0 + jt;              // this block's batch
        if (tid < OUTs) {
            float acc = b_fc[tid];
            const float* wr = W_fc + tid * Hh;
            #pragma unroll 8
            for (int k = 0; k < Hh; ++k)
                acc += hf[(k << 7) + bb] * wr[k];
            out[bb * OUTs + tid] = acc;
        }
    }
}

// ---------------- launcher ----------------
extern "C" void kernel_launch(void* const* d_in, const int* in_sizes, int n_in,
                              void* d_out, int out_size) {
    const float* x    = (const float*)d_in[0];
    // d_in[1] = input_lengths (unused by the reference)
    const float* W_ih = (const float*)d_in[2];
    const float* W_hh = (const float*)d_in[3];
    const float* b_ih = (const float*)d_in[4];
    const float* b_hh = (const float*)d_in[5];
    // d_in[6], d_in[7] = W_xi, b_xi — dead code (memory never affects output)
    const float* W_fc = (const float*)d_in[8];
    const float* b_fc = (const float*)d_in[9];
    float* out = (float*)d_out;

    // smem: 32768 (sH) + 34816 (sR padded: 256*17*8) = 67584 bytes
    cudaFuncSetAttribute(step_kernel, cudaFuncAttributeMaxDynamicSharedMemorySize, 67584);

    pre_kernel<<<dim3(Tt, 8), 128>>>(x, W_ih, b_ih, b_hh);
    step_kernel<<<NB, 512, 67584>>>(W_hh, W_fc, b_fc, out);
}

// round 7
// speedup vs baseline: 1.5965x; 1.2144x over previous
#include <cuda_runtime.h>

#define Bsz   128
#define Tt    512
#define INs   27
#define G4    1024
#define NB    128
#define OUTs  128
#define Dring 4

// ---- persistent device scratch (static: no runtime allocation) ----
__device__ float g_G[(size_t)Tt * G4 * Bsz];                 // [t][g(1024)][b]
__device__ unsigned long long g_hx[Dring * 256 * 128];       // {f32 h, u32 tag} [slot][k][b]

// ---------------- helpers ----------------
__device__ __forceinline__ void fma2(unsigned long long& d, unsigned long long a, unsigned long long b) {
    asm("fma.rn.f32x2 %0, %1, %2, %0;" : "+l"(d) : "l"(a), "l"(b));
}
__device__ __forceinline__ unsigned long long ldrx(const unsigned long long* p) {
    unsigned long long v;
    asm volatile("ld.relaxed.gpu.global.u64 %0, [%1];" : "=l"(v) : "l"(p) : "memory");
    return v;
}
__device__ __forceinline__ void strx(unsigned long long* p, unsigned long long v) {
    asm volatile("st.relaxed.gpu.global.u64 [%0], %1;" :: "l"(p), "l"(v) : "memory");
}
__device__ __forceinline__ float sigf(float x) {
    return __fdividef(1.f, 1.f + __expf(-x));
}
__device__ __forceinline__ float tanhf_(float x) {
    float e = __expf(-2.f * fabsf(x));
    float r = __fdividef(1.f - e, 1.f + e);
    return copysignf(r, x);
}

// ---------------- kernels ----------------
// G[t][g][b] = b_ih[g] + b_hh[g] + sum_{k<27} x[b][t][k] * W_ih[g][k]
// Also seed the tagged-h ring: slot 0 = {0.0f, tag 0} (h_0), slots 1..3 = sentinel.
__global__ void pre_kernel(const float* __restrict__ x,
                           const float* __restrict__ W_ih,
                           const float* __restrict__ b_ih,
                           const float* __restrict__ b_hh) {
    __shared__ float xs[Bsz * INs];
    const int t   = blockIdx.x;
    const int gc  = blockIdx.y;       // 0..7, 128 gates each
    const int tid = threadIdx.x;      // = b  (blockDim.x == 128)

    if (gc == 0) {                    // 65536 threads clear 131072 ring entries
        int e = t * 128 + tid;
        #pragma unroll
        for (int r = 0; r < 2; ++r, e += 65536) {
            unsigned tag = (e < 32768) ? 0u : 0x80000000u;   // slot 0 : sentinel
            g_hx[e] = ((unsigned long long)tag << 32);        // value bits = 0.0f
        }
    }

    for (int i = tid; i < Bsz * INs; i += 128) {
        int b = i / INs, k = i - b * INs;
        xs[i] = x[((size_t)b * Tt + t) * INs + k];
    }
    __syncthreads();
    float xr[INs];
    #pragma unroll
    for (int k = 0; k < INs; ++k) xr[k] = xs[tid * INs + k];

    for (int g0 = 0; g0 < 128; ++g0) {
        int g = (gc << 7) + g0;
        float acc = b_ih[g] + b_hh[g];
        const float* wr = W_ih + g * 47;   // NN_IN = 47, only first 27 cols used
        #pragma unroll
        for (int k = 0; k < INs; ++k) acc += xr[k] * __ldg(wr + k);
        g_G[((size_t)t * G4 + g) * Bsz + tid] = acc;
    }
}

// Persistent sequential LSTM. 128 blocks = 4 b-groups(32 batches) x 32 j-tiles(8 j).
// Synchronization is purely data-driven: h values carry their step tag in the
// upper 32 bits of a single 64-bit word; consumers poll exactly what they need.
__global__ void __launch_bounds__(512, 1)
step_kernel(const float* __restrict__ W_hh,
            const float* __restrict__ W_fc,
            const float* __restrict__ b_fc,
            float* __restrict__ out) {
    extern __shared__ float sm[];
    float*              sH  = sm;                                  // 8192 floats: [k][32 b]
    unsigned long long* sRd = (unsigned long long*)(sm + 8192);    // 256 rows x 17 u64 (padded)
    float*              sRf = (float*)sRd;

    const int tid  = threadIdx.x;
    const int warp = tid >> 5;
    const int lane = tid & 31;
    const int g    = blockIdx.x >> 5;         // b-group 0..3
    const int jt   = blockIdx.x & 31;         // j-tile 0..31
    const int b0   = g << 5;
    const int j0   = jt << 3;

    const int pw = warp & 1;                  // batch pairset: pairs [8pw, 8pw+8)
    const int ks = warp >> 1;                 // k-split: k in [32ks, 32ks+32)
    const int kb = ks << 5;

    // this lane's gate-row: row = jl*4 + gate
    const int jl_r   = lane >> 2;
    const int gate_r = lane & 3;
    const int row_g  = (gate_r << 8) + j0 + jl_r;    // W_hh row (gate*256 + j)

    // ---- W slice (32 k) in registers for the whole kernel ----
    float w[32];
    {
        const float* wp = W_hh + ((size_t)row_g << 8) + kb;
        #pragma unroll
        for (int kk = 0; kk < 32; ++kk) w[kk] = wp[kk];
    }

    // epilogue mapping (first 256 threads): ej = j-local (warp), eb = batch-local (lane)
    const int ej = warp & 7;
    const int eb = lane;
    const bool epi = (tid < 256);

    float cold = 0.f;                          // c stays in a register for all steps

    for (int s = 0; s < Tt; ++s) {
        // prefetch G (independent of h_s) — DRAM latency hides behind the poll
        float gp0 = 0.f, gp1 = 0.f, gp2 = 0.f, gp3 = 0.f;
        if (epi) {
            size_t gb = ((size_t)s << 10) + j0 + ej;             // s*1024 + j
            gp0 = g_G[(gb        ) * Bsz + eb + b0];
            gp1 = g_G[(gb +  256 ) * Bsz + eb + b0];
            gp2 = g_G[(gb +  512 ) * Bsz + eb + b0];
            gp3 = g_G[(gb +  768 ) * Bsz + eb + b0];
        }

        // ---- poll-stage h_s (tag == s) into sH: 16 elems/thread, 2 waves of 8 ----
        // wave wv covers k = warp + wv*128 + j*16   (j = 0..7)
        {
            const unsigned long long* hx = g_hx + ((size_t)(s & 3) << 15);
            const unsigned wanted = (unsigned)s;
            #pragma unroll
            for (int wv = 0; wv < 2; ++wv) {
                unsigned long long v[8];
                const unsigned long long* p0 = hx + ((warp + (wv << 7)) << 7) + b0 + lane;
                #pragma unroll
                for (int j = 0; j < 8; ++j) v[j] = ldrx(p0 + (j << 11));   // k += 16 -> +2048
                bool all;
                do {
                    all = true;
                    #pragma unroll
                    for (int j = 0; j < 8; ++j) {
                        if ((unsigned)(v[j] >> 32) != wanted) {
                            v[j] = ldrx(p0 + (j << 11));
                            all = false;
                        }
                    }
                } while (!all);
                #pragma unroll
                for (int j = 0; j < 8; ++j)
                    sH[tid + ((wv * 8 + j) << 9)] = __uint_as_float((unsigned)v[j]);
            }
        }
        __syncthreads();

        // ---- GEMM: W in regs, h via broadcast LDS; 8 pairs x 32 k per lane ----
        unsigned long long acc[8];
        #pragma unroll
        for (int a = 0; a < 8; ++a) acc[a] = 0ULL;

        #pragma unroll
        for (int kk = 0; kk < 32; ++kk) {
            const ulonglong2* hp = (const ulonglong2*)(sH + ((kb + kk) << 5) + (pw << 4));
            ulonglong2 hA = hp[0];             // pairs 0,1 (broadcast)
            ulonglong2 hB = hp[1];             // pairs 2,3
            ulonglong2 hC = hp[2];             // pairs 4,5
            ulonglong2 hD = hp[3];             // pairs 6,7
            unsigned long long wd;
            asm("mov.b64 %0, {%1, %1};" : "=l"(wd) : "f"(w[kk]));
            fma2(acc[0], hA.x, wd); fma2(acc[1], hA.y, wd);
            fma2(acc[2], hB.x, wd); fma2(acc[3], hB.y, wd);
            fma2(acc[4], hC.x, wd); fma2(acc[5], hC.y, wd);
            fma2(acc[6], hD.x, wd); fma2(acc[7], hD.y, wd);
        }

        // ---- partials to padded shared: row = (ks*32 + gate-row), 16 pairs + pad ----
        {
            int base = ((ks << 5) + lane) * 17 + (pw << 3);
            #pragma unroll
            for (int p = 0; p < 8; ++p) sRd[base + p] = acc[p];
        }
        __syncthreads();

        // ---- epilogue: sum 8 k-splits, add G, LSTM cell update, publish tagged h ----
        if (epi) {
            float v0 = gp0, v1 = gp1, v2 = gp2, v3 = gp3;
            #pragma unroll
            for (int kss = 0; kss < 8; ++kss) {
                int rbase = (kss << 5) + (ej << 2);
                v0 += sRf[(rbase + 0) * 34 + eb];
                v1 += sRf[(rbase + 1) * 34 + eb];
                v2 += sRf[(rbase + 2) * 34 + eb];
                v3 += sRf[(rbase + 3) * 34 + eb];
            }
            float ig = sigf(v0), fg = sigf(v1);
            float gg = tanhf_(v2), og = sigf(v3);
            float cn = fg * cold + ig * gg;
            float hn = og * tanhf_(cn);
            cold = cn;
            unsigned long long pkt =
                ((unsigned long long)(unsigned)(s + 1) << 32) | (unsigned)__float_as_uint(hn);
            strx(g_hx + ((size_t)((s + 1) & 3) << 15) + (((j0 + ej) << 7) + b0 + eb), pkt);
        }
        // no block-wide sync needed: next staging is gated by the tags themselves
    }

    // ---- classifier head: poll h_T (tag 512, slot 0) for this block's batch ----
    {
        const int bb = b0 + jt;                  // this block's batch
        const unsigned long long* hx = g_hx;     // slot 512 % 4 == 0
        if (tid < 256) {
            const unsigned long long* p = hx + ((size_t)tid << 7) + bb;
            unsigned long long v = ldrx(p);
            while ((unsigned)(v >> 32) != (unsigned)Tt) v = ldrx(p);
            sH[tid] = __uint_as_float((unsigned)v);
        }
        __syncthreads();
        if (tid < OUTs) {
            float acc = b_fc[tid];
            const float* wr = W_fc + tid * 256;
            #pragma unroll 8
            for (int k = 0; k < 256; ++k)
                acc += sH[k] * wr[k];
            out[bb * OUTs + tid] = acc;
        }
    }
}

// ---------------- launcher ----------------
extern "C" void kernel_launch(void* const* d_in, const int* in_sizes, int n_in,
                              void* d_out, int out_size) {
    const float* x    = (const float*)d_in[0];
    // d_in[1] = input_lengths (unused by the reference)
    const float* W_ih = (const float*)d_in[2];
    const float* W_hh = (const float*)d_in[3];
    const float* b_ih = (const float*)d_in[4];
    const float* b_hh = (const float*)d_in[5];
    // d_in[6], d_in[7] = W_xi, b_xi — dead code (memory never affects output)
    const float* W_fc = (const float*)d_in[8];
    const float* b_fc = (const float*)d_in[9];
    float* out = (float*)d_out;

    // smem: 32768 (sH) + 34816 (sR padded: 256*17*8) = 67584 bytes
    cudaFuncSetAttribute(step_kernel, cudaFuncAttributeMaxDynamicSharedMemorySize, 67584);

    pre_kernel<<<dim3(Tt, 8), 128>>>(x, W_ih, b_ih, b_hh);
    step_kernel<<<NB, 512, 67584>>>(W_hh, W_fc, b_fc, out);
}

// round 8
// speedup vs baseline: 1.7191x; 1.0768x over previous
#include <cuda_runtime.h>

#define Bsz   128
#define Tt    512
#define INs   27
#define G4    1024
#define NB    128
#define OUTs  128

// ---- persistent device scratch (static: no runtime allocation) ----
__device__ float g_G[(size_t)Tt * G4 * Bsz];            // [t][g(1024)][b]
// tagged-h ring: u64 = {h[2b+1] | h[2b]}, each fp32 carries step-tag in 2 LSBs.
// layout [slot(4)][k(256)][bpair(64)]
__device__ unsigned long long g_hx[4 * 256 * 64];

// ---------------- helpers ----------------
__device__ __forceinline__ void fma2(unsigned long long& d, unsigned long long a, unsigned long long b) {
    asm("fma.rn.f32x2 %0, %1, %2, %0;" : "+l"(d) : "l"(a), "l"(b));
}
__device__ __forceinline__ unsigned long long ldrx(const unsigned long long* p) {
    unsigned long long v;
    asm volatile("ld.relaxed.gpu.global.u64 %0, [%1];" : "=l"(v) : "l"(p) : "memory");
    return v;
}
__device__ __forceinline__ void strx(unsigned long long* p, unsigned long long v) {
    asm volatile("st.relaxed.gpu.global.u64 [%0], %1;" :: "l"(p), "l"(v) : "memory");
}
__device__ __forceinline__ float sigf(float x) {
    return __fdividef(1.f, 1.f + __expf(-x));
}
__device__ __forceinline__ float tanhf_(float x) {
    float e = __expf(-2.f * fabsf(x));
    float r = __fdividef(1.f - e, 1.f + e);
    return copysignf(r, x);
}

// ---------------- kernels ----------------
// G[t][g][b] = b_ih[g] + b_hh[g] + sum_{k<27} x[b][t][k] * W_ih[g][k]
// Also seed the tagged ring: slot 0 = h_0 = 0.0f (tag bits 0), slots 1..3 = tag 3 sentinel.
__global__ void pre_kernel(const float* __restrict__ x,
                           const float* __restrict__ W_ih,
                           const float* __restrict__ b_ih,
                           const float* __restrict__ b_hh) {
    __shared__ float xs[Bsz * INs];
    const int t   = blockIdx.x;
    const int gc  = blockIdx.y;       // 0..7, 128 gates each
    const int tid = threadIdx.x;      // = b  (blockDim.x == 128)

    if (gc == 0) {                    // 512*128 = 65536 threads cover 65536 ring entries
        int e = t * 128 + tid;
        g_hx[e] = (e < 16384) ? 0ULL : 0x0000000300000003ULL;
    }

    for (int i = tid; i < Bsz * INs; i += 128) {
        int b = i / INs, k = i - b * INs;
        xs[i] = x[((size_t)b * Tt + t) * INs + k];
    }
    __syncthreads();
    float xr[INs];
    #pragma unroll
    for (int k = 0; k < INs; ++k) xr[k] = xs[tid * INs + k];

    for (int g0 = 0; g0 < 128; ++g0) {
        int g = (gc << 7) + g0;
        float acc = b_ih[g] + b_hh[g];
        const float* wr = W_ih + g * 47;   // NN_IN = 47, only first 27 cols used
        #pragma unroll
        for (int k = 0; k < INs; ++k) acc += xr[k] * __ldg(wr + k);
        g_G[((size_t)t * G4 + g) * Bsz + tid] = acc;
    }
}

// Persistent sequential LSTM. 128 blocks = 4 b-groups(32 batches) x 32 j-tiles(8 j).
// Warp (pw = warp&1: 16-batch half; ks = warp>>5... warp>>1: 32-k split) polls its own
// slice of tagged h, stages to its PRIVATE sH region (syncwarp only), GEMMs, and the
// 8-way k-split partials are reduced through double-buffered sR (one block sync/step).
__global__ void __launch_bounds__(512, 1)
step_kernel(const float* __restrict__ W_hh,
            const float* __restrict__ W_fc,
            const float* __restrict__ b_fc,
            float* __restrict__ out) {
    extern __shared__ float sm[];
    float*              sH  = sm;                                  // 8192 floats: 16 warp regions x [32k][16b]
    unsigned long long* sRd = (unsigned long long*)(sm + 8192);    // 2 bufs x 256 rows x 17 u64

    const int tid  = threadIdx.x;
    const int warp = tid >> 5;
    const int lane = tid & 31;
    const int g    = blockIdx.x >> 5;         // b-group 0..3
    const int jt   = blockIdx.x & 31;         // j-tile 0..31
    const int b0   = g << 5;
    const int j0   = jt << 3;

    const int pw = warp & 1;                  // batch half: b_local in [16pw, 16pw+16)
    const int ks = warp >> 1;                 // k-split: k in [32ks, 32ks+32)
    const int kb = ks << 5;

    // this lane's gate-row: row = jl*4 + gate
    const int jl_r   = lane >> 2;
    const int gate_r = lane & 3;
    const int row_g  = (gate_r << 8) + j0 + jl_r;    // W_hh row (gate*256 + j)

    // ---- W slice (32 k) in registers for the whole kernel ----
    float w[32];
    {
        const float* wp = W_hh + ((size_t)row_g << 8) + kb;
        #pragma unroll
        for (int kk = 0; kk < 32; ++kk) w[kk] = wp[kk];
    }

    // staging lane mapping: 4 k-rows x 8 bpairs
    const int jgrp = lane >> 3;               // k_local = jgrp + 4j
    const int bp   = lane & 7;                // bpair within 16-batch half
    float* sHw = sH + (warp << 9);            // private 512-float region [k_local(32)][b(16)]

    // epilogue mapping (first 256 threads): ej = j-local (warp 0..7), eb = batch (lane)
    const int ej = warp & 7;
    const int eb = lane;
    const bool epi = (tid < 256);

    float cold = 0.f;                          // c stays in a register for all steps

    for (int s = 0; s < Tt; ++s) {
        // prefetch G (independent of h_s) — DRAM latency hides behind the poll
        float gp0 = 0.f, gp1 = 0.f, gp2 = 0.f, gp3 = 0.f;
        if (epi) {
            size_t gb = ((size_t)s << 10) + j0 + ej;             // s*1024 + j
            gp0 = g_G[(gb        ) * Bsz + eb + b0];
            gp1 = g_G[(gb +  256 ) * Bsz + eb + b0];
            gp2 = g_G[(gb +  512 ) * Bsz + eb + b0];
            gp3 = g_G[(gb +  768 ) * Bsz + eb + b0];
        }

        // ---- poll-stage h_s slice (8 u64/lane) into PRIVATE region ----
        {
            const unsigned long long* hx = g_hx + ((size_t)(s & 3) << 14);
            const unsigned long long pat =
                (unsigned long long)((unsigned)(s >> 2) & 3u) * 0x0000000100000001ULL;
            const unsigned long long* p0 =
                hx + (((size_t)(kb + jgrp)) << 6) + (g << 4) + (pw << 3) + bp;
            unsigned long long v[8];
            #pragma unroll
            for (int j = 0; j < 8; ++j) v[j] = ldrx(p0 + (j << 8));   // k += 4 -> +256 u64
            int spins = 0;
            bool all;
            do {
                all = true;
                #pragma unroll
                for (int j = 0; j < 8; ++j) {
                    if ((v[j] & 0x0000000300000003ULL) != pat) {
                        v[j] = ldrx(p0 + (j << 8));
                        all = false;
                    }
                }
                if (!all && ++spins > 2) __nanosleep(40);
            } while (!all);
            unsigned long long* dst = (unsigned long long*)sHw;
            #pragma unroll
            for (int j = 0; j < 8; ++j)
                dst[((jgrp + (j << 2)) << 3) + bp] = v[j];
        }
        __syncwarp();

        // ---- GEMM: W in regs, h via broadcast LDS from private region ----
        unsigned long long acc[8];
        #pragma unroll
        for (int a = 0; a < 8; ++a) acc[a] = 0ULL;

        #pragma unroll
        for (int kk = 0; kk < 32; ++kk) {
            const ulonglong2* hp = (const ulonglong2*)(sHw + (kk << 4));
            ulonglong2 hA = hp[0];             // pairs 0,1 (broadcast)
            ulonglong2 hB = hp[1];             // pairs 2,3
            ulonglong2 hC = hp[2];             // pairs 4,5
            ulonglong2 hD = hp[3];             // pairs 6,7
            unsigned long long wd;
            asm("mov.b64 %0, {%1, %1};" : "=l"(wd) : "f"(w[kk]));
            fma2(acc[0], hA.x, wd); fma2(acc[1], hA.y, wd);
            fma2(acc[2], hB.x, wd); fma2(acc[3], hB.y, wd);
            fma2(acc[4], hC.x, wd); fma2(acc[5], hC.y, wd);
            fma2(acc[6], hD.x, wd); fma2(acc[7], hD.y, wd);
        }

        // ---- partials to double-buffered padded shared ----
        {
            unsigned long long* sRb = sRd + (s & 1) * 4352;
            int base = ((ks << 5) + lane) * 17 + (pw << 3);
            #pragma unroll
            for (int p = 0; p < 8; ++p) sRb[base + p] = acc[p];
        }
        __syncthreads();                       // the ONLY block sync per step

        // ---- epilogue: sum 8 k-splits, add G, LSTM cell, publish tagged pair ----
        if (epi) {
            const float* sRf = (const float*)(sRd + (s & 1) * 4352);
            float v0 = gp0, v1 = gp1, v2 = gp2, v3 = gp3;
            #pragma unroll
            for (int kss = 0; kss < 8; ++kss) {
                int rbase = (kss << 5) + (ej << 2);
                v0 += sRf[(rbase + 0) * 34 + eb];
                v1 += sRf[(rbase + 1) * 34 + eb];
                v2 += sRf[(rbase + 2) * 34 + eb];
                v3 += sRf[(rbase + 3) * 34 + eb];
            }
            float ig = sigf(v0), fg = sigf(v1);
            float gg = tanhf_(v2), og = sigf(v3);
            float cn = fg * cold + ig * gg;
            float hn = og * tanhf_(cn);
            cold = cn;
            unsigned tagv = ((unsigned)(s + 1) >> 2) & 3u;
            unsigned uv  = (__float_as_uint(hn) & ~3u) | tagv;
            unsigned hiv = __shfl_xor_sync(0xffffffffu, uv, 1);
            if (!(eb & 1)) {
                unsigned long long pkt =
                    (unsigned long long)uv | ((unsigned long long)hiv << 32);
                strx(g_hx + ((size_t)((s + 1) & 3) << 14)
                          + (((j0 + ej) << 6) + (g << 4) + (eb >> 1)), pkt);
            }
        }
        // no trailing sync: sH is warp-private; sR buffer parity protects the reduce
    }

    // ---- classifier head: poll h_T (slot 0, tag 0) for this block's batch ----
    {
        const int bb = b0 + jt;                  // this block's batch
        const unsigned wantT = ((unsigned)Tt >> 2) & 3u;
        if (tid < 256) {
            const unsigned long long* p = g_hx + ((size_t)tid << 6) + (bb >> 1);
            const unsigned sh = (bb & 1) << 5;
            unsigned long long v = ldrx(p);
            while (((v >> sh) & 3ULL) != wantT) { __nanosleep(40); v = ldrx(p); }
            sH[tid] = __uint_as_float((unsigned)(v >> sh));
        }
        __syncthreads();
        if (tid < OUTs) {
            float acc = b_fc[tid];
            const float* wr = W_fc + tid * 256;
            #pragma unroll 8
            for (int k = 0; k < 256; ++k)
                acc += sH[k] * wr[k];
            out[bb * OUTs + tid] = acc;
        }
    }
}

// ---------------- launcher ----------------
extern "C" void kernel_launch(void* const* d_in, const int* in_sizes, int n_in,
                              void* d_out, int out_size) {
    const float* x    = (const float*)d_in[0];
    // d_in[1] = input_lengths (unused by the reference)
    const float* W_ih = (const float*)d_in[2];
    const float* W_hh = (const float*)d_in[3];
    const float* b_ih = (const float*)d_in[4];
    const float* b_hh = (const float*)d_in[5];
    // d_in[6], d_in[7] = W_xi, b_xi — dead code (memory never affects output)
    const float* W_fc = (const float*)d_in[8];
    const float* b_fc = (const float*)d_in[9];
    float* out = (float*)d_out;

    // smem: 32768 (sH) + 2*34816 (sR double buffer) = 102400 bytes
    cudaFuncSetAttribute(step_kernel, cudaFuncAttributeMaxDynamicSharedMemorySize, 102400);

    pre_kernel<<<dim3(Tt, 8), 128>>>(x, W_ih, b_ih, b_hh);
    step_kernel<<<NB, 512, 102400>>>(W_hh, W_fc, b_fc, out);
}

// round 9
// speedup vs baseline: 2.0789x; 1.2093x over previous
#include <cuda_runtime.h>

#define Bsz   128
#define Tt    512
#define INs   27
#define G4    1024
#define NB    128
#define OUTs  128

// ---- persistent device scratch (static: no runtime allocation) ----
__device__ float g_G[(size_t)Tt * G4 * Bsz];        // [t][g(1024)][b(128)]
// tagged-h ring: u64 = {h[2b+1] | h[2b]}, each fp32 carries step-tag in 2 LSBs.
// layout [slot(4)][grp(16)][k(256)][bpair(4)]
__device__ unsigned long long g_hx[4 * 16 * 256 * 4];

// ---------------- helpers ----------------
__device__ __forceinline__ void fma2(unsigned long long& d, unsigned long long a, unsigned long long b) {
    asm("fma.rn.f32x2 %0, %1, %2, %0;" : "+l"(d) : "l"(a), "l"(b));
}
__device__ __forceinline__ void add2(unsigned long long& d, unsigned long long a) {
    asm("add.rn.f32x2 %0, %0, %1;" : "+l"(d) : "l"(a));
}
__device__ __forceinline__ unsigned long long ldrx(const unsigned long long* p) {
    unsigned long long v;
    asm volatile("ld.relaxed.gpu.global.u64 %0, [%1];" : "=l"(v) : "l"(p) : "memory");
    return v;
}
__device__ __forceinline__ void strx(unsigned long long* p, unsigned long long v) {
    asm volatile("st.relaxed.gpu.global.u64 [%0], %1;" :: "l"(p), "l"(v) : "memory");
}
__device__ __forceinline__ float sigf(float x) {
    return __fdividef(1.f, 1.f + __expf(-x));
}
__device__ __forceinline__ float tanhf_(float x) {
    float e = __expf(-2.f * fabsf(x));
    float r = __fdividef(1.f - e, 1.f + e);
    return copysignf(r, x);
}

// ---------------- kernels ----------------
// G[t][g][b] = b_ih[g] + b_hh[g] + sum_{k<27} x[b][t][k] * W_ih[g][k]
// Also seed ring: slot 0 = h_0 = 0.0f (tag 0), slots 1..3 = tag-3 sentinel
// (first wanted tag for every slot is 0, so the sentinel never matches early).
__global__ void pre_kernel(const float* __restrict__ x,
                           const float* __restrict__ W_ih,
                           const float* __restrict__ b_ih,
                           const float* __restrict__ b_hh) {
    __shared__ float xs[Bsz * INs];
    const int t   = blockIdx.x;
    const int gc  = blockIdx.y;       // 0..7, 128 gates each
    const int tid = threadIdx.x;      // = b  (blockDim.x == 128)

    if (gc == 0) {                    // 512*128 threads cover 65536 ring entries
        int e = t * 128 + tid;
        g_hx[e] = (e < 16384) ? 0ULL : 0x0000000300000003ULL;
    }

    for (int i = tid; i < Bsz * INs; i += 128) {
        int b = i / INs, k = i - b * INs;
        xs[i] = x[((size_t)b * Tt + t) * INs + k];
    }
    __syncthreads();
    float xr[INs];
    #pragma unroll
    for (int k = 0; k < INs; ++k) xr[k] = xs[tid * INs + k];

    for (int g0 = 0; g0 < 128; ++g0) {
        int g = (gc << 7) + g0;
        float acc = b_ih[g] + b_hh[g];
        const float* wr = W_ih + g * 47;   // NN_IN = 47, only first 27 cols used
        #pragma unroll
        for (int k = 0; k < INs; ++k) acc += xr[k] * __ldg(wr + k);
        g_G[((size_t)t * G4 + g) * Bsz + tid] = acc;
    }
}

// Persistent sequential LSTM. 128 blocks = 16 batch-groups(8 batches) x 8 j-tiles(32 j).
// Block holds 128 gate-rows (4 gates x 32 j) x 256 k of W_hh in REGISTERS (2 rows/thread).
// k-split warppair ks polls h[32ks..32ks+32) — published by exactly ONE sibling block.
__global__ void __launch_bounds__(512, 1)
step_kernel(const float* __restrict__ W_hh,
            const float* __restrict__ W_fc,
            const float* __restrict__ b_fc,
            float* __restrict__ out) {
    extern __shared__ unsigned long long smu[];
    unsigned long long* sHd = smu;            // 1024 u64 (8KB): [ks(8)][k_local*4+bp]
    unsigned long long* sRd = smu + 1024;     // 2 bufs x 4096 u64: [ks][bp][row]

    const int tid  = threadIdx.x;
    const int warp = tid >> 5;
    const int lane = tid & 31;
    const int grp  = blockIdx.x >> 3;         // batch-group 0..15
    const int jt   = blockIdx.x & 7;          // j-tile 0..7
    const int b0   = grp << 3;
    const int j0   = jt << 5;

    const int ks   = warp >> 1;               // k-split 0..7: k in [32ks, 32ks+32)
    const int half = warp & 1;
    const int rg   = (half << 5) + lane;      // row-group 0..63
    const int r0   = rg << 1;                 // rows r0, r0+1 (same gate, adjacent j)
    const int gate = r0 >> 5;
    const int jl0  = r0 & 31;

    // ---- W slice: 2 rows x 32 k in registers for the whole kernel ----
    float w0[32], w1[32];
    {
        const float* wp0 = W_hh + (((gate << 8) + j0 + jl0) << 8) + (ks << 5);
        #pragma unroll
        for (int kk = 0; kk < 32; ++kk) { w0[kk] = wp0[kk]; w1[kk] = wp0[256 + kk]; }
    }

    // poll mapping: thread handles u64 idx rg and rg+64 of its ks slice
    const size_t pbase = ((size_t)grp << 10) + (ks << 7) + rg;

    // epilogue mapping (first 128 threads): ejl = j-local 0..31, ebp = bpair 0..3
    const bool epi = (tid < 128);
    const int ejl = tid >> 2;
    const int ebp = tid & 3;
    const size_t pubbase = ((size_t)grp << 10) + ((j0 + ejl) << 2) + ebp;

    float c0 = 0.f, c1 = 0.f;                  // cell state in registers

    for (int s = 0; s < Tt; ++s) {
        // prefetch G (independent of h_s) — latency hides behind the poll
        float2 gI, gF, gG2, gO;
        if (epi) {
            size_t tb = (((size_t)s << 10) + j0 + ejl) << 7;
            const float* gp = g_G + tb + b0 + (ebp << 1);
            gI  = *(const float2*)(gp);
            gF  = *(const float2*)(gp + (256 << 7));
            gG2 = *(const float2*)(gp + (512 << 7));
            gO  = *(const float2*)(gp + (768 << 7));
        }

        // ---- poll h_s slice (2 u64/thread) ----
        {
            const unsigned long long* p0 = g_hx + (((size_t)(s & 3)) << 14) + pbase;
            const unsigned long long pat =
                (unsigned long long)((unsigned)(s >> 2) & 3u) * 0x0000000100000001ULL;
            unsigned long long v0 = ldrx(p0), v1 = ldrx(p0 + 64);
            int spins = 0;
            while (((v0 & 0x0000000300000003ULL) != pat) ||
                   ((v1 & 0x0000000300000003ULL) != pat)) {
                if (++spins > 2) __nanosleep(40);
                if ((v0 & 0x0000000300000003ULL) != pat) v0 = ldrx(p0);
                if ((v1 & 0x0000000300000003ULL) != pat) v1 = ldrx(p0 + 64);
            }
            sHd[(ks << 7) + rg]      = v0;
            sHd[(ks << 7) + rg + 64] = v1;
        }
        __syncthreads();

        // ---- GEMM: 2 rows x 4 bpairs x 32 k; h broadcast LDS, W in regs ----
        unsigned long long a0[4], a1[4];
        #pragma unroll
        for (int p = 0; p < 4; ++p) { a0[p] = 0ULL; a1[p] = 0ULL; }

        #pragma unroll
        for (int kk = 0; kk < 32; ++kk) {
            const ulonglong2* hh = (const ulonglong2*)(sHd + (ks << 7) + (kk << 2));
            ulonglong2 hA = hh[0];             // bpairs 0,1 (broadcast)
            ulonglong2 hB = hh[1];             // bpairs 2,3
            unsigned long long wd0, wd1;
            asm("mov.b64 %0, {%1, %1};" : "=l"(wd0) : "f"(w0[kk]));
            asm("mov.b64 %0, {%1, %1};" : "=l"(wd1) : "f"(w1[kk]));
            fma2(a0[0], hA.x, wd0); fma2(a0[1], hA.y, wd0);
            fma2(a0[2], hB.x, wd0); fma2(a0[3], hB.y, wd0);
            fma2(a1[0], hA.x, wd1); fma2(a1[1], hA.y, wd1);
            fma2(a1[2], hB.x, wd1); fma2(a1[3], hB.y, wd1);
        }

        // ---- partials: sR[buf][ks][bp][row], rows (r0, r0+1) as one 16B store ----
        {
            unsigned long long* sRb = sRd + ((s & 1) << 12);
            #pragma unroll
            for (int p = 0; p < 4; ++p) {
                ulonglong2 pr; pr.x = a0[p]; pr.y = a1[p];
                *(ulonglong2*)(sRb + (ks << 9) + (p << 7) + r0) = pr;
            }
        }
        __syncthreads();

        // ---- epilogue: sum 8 k-splits per gate (f32x2), LSTM, publish tagged pair ----
        if (epi) {
            const unsigned long long* sRb = sRd + ((s & 1) << 12);
            unsigned long long vi, vf, vg, vo;
            asm("mov.b64 %0, {%1, %2};" : "=l"(vi) : "f"(gI.x),  "f"(gI.y));
            asm("mov.b64 %0, {%1, %2};" : "=l"(vf) : "f"(gF.x),  "f"(gF.y));
            asm("mov.b64 %0, {%1, %2};" : "=l"(vg) : "f"(gG2.x), "f"(gG2.y));
            asm("mov.b64 %0, {%1, %2};" : "=l"(vo) : "f"(gO.x),  "f"(gO.y));
            int base = (ebp << 7) + ejl;
            #pragma unroll
            for (int k2 = 0; k2 < 8; ++k2) {
                const unsigned long long* rr = sRb + (k2 << 9) + base;
                add2(vi, rr[0]);
                add2(vf, rr[32]);
                add2(vg, rr[64]);
                add2(vo, rr[96]);
            }
            float iL, iH, fL, fH, gL, gH, oL, oH;
            asm("mov.b64 {%0, %1}, %2;" : "=f"(iL), "=f"(iH) : "l"(vi));
            asm("mov.b64 {%0, %1}, %2;" : "=f"(fL), "=f"(fH) : "l"(vf));
            asm("mov.b64 {%0, %1}, %2;" : "=f"(gL), "=f"(gH) : "l"(vg));
            asm("mov.b64 {%0, %1}, %2;" : "=f"(oL), "=f"(oH) : "l"(vo));
            c0 = sigf(fL) * c0 + sigf(iL) * tanhf_(gL);
            c1 = sigf(fH) * c1 + sigf(iH) * tanhf_(gH);
            float h0 = sigf(oL) * tanhf_(c0);
            float h1 = sigf(oH) * tanhf_(c1);
            unsigned tagv = ((unsigned)(s + 1) >> 2) & 3u;
            unsigned u0 = (__float_as_uint(h0) & ~3u) | tagv;
            unsigned u1 = (__float_as_uint(h1) & ~3u) | tagv;
            unsigned long long pkt = (unsigned long long)u0 | ((unsigned long long)u1 << 32);
            strx(g_hx + (((size_t)((s + 1) & 3)) << 14) + pubbase, pkt);
        }
        // no trailing sync: sR buffer parity protects the reduce; polls gate staging
    }

    // ---- classifier head: poll h_T (slot 0, tag 0) for this block's batch ----
    {
        float* sHf = (float*)sHd;
        const int bb = blockIdx.x;               // batch = block id
        if (tid < 256) {
            const unsigned long long* p =
                g_hx + (((size_t)(bb >> 3)) << 10) + (tid << 2) + ((bb & 7) >> 1);
            const unsigned sh = (bb & 1) << 5;
            unsigned long long v = ldrx(p);
            while ((unsigned)((v >> sh) & 3ULL) != 0u) { __nanosleep(40); v = ldrx(p); }
            sHf[tid] = __uint_as_float((unsigned)(v >> sh));
        }
        __syncthreads();
        if (tid < OUTs) {
            float acc = b_fc[tid];
            const float* wr = W_fc + tid * 256;
            #pragma unroll 8
            for (int k = 0; k < 256; ++k)
                acc += sHf[k] * wr[k];
            out[bb * OUTs + tid] = acc;
        }
    }
}

// ---------------- launcher ----------------
extern "C" void kernel_launch(void* const* d_in, const int* in_sizes, int n_in,
                              void* d_out, int out_size) {
    const float* x    = (const float*)d_in[0];
    // d_in[1] = input_lengths (unused by the reference)
    const float* W_ih = (const float*)d_in[2];
    const float* W_hh = (const float*)d_in[3];
    const float* b_ih = (const float*)d_in[4];
    const float* b_hh = (const float*)d_in[5];
    // d_in[6], d_in[7] = W_xi, b_xi — dead code (memory never affects output)
    const float* W_fc = (const float*)d_in[8];
    const float* b_fc = (const float*)d_in[9];
    float* out = (float*)d_out;

    // smem: 8192 (sHd) + 2*32768 (sRd double buffer) = 73728 bytes
    cudaFuncSetAttribute(step_kernel, cudaFuncAttributeMaxDynamicSharedMemorySize, 73728);

    pre_kernel<<<dim3(Tt, 8), 128>>>(x, W_ih, b_ih, b_hh);
    step_kernel<<<NB, 512, 73728>>>(W_hh, W_fc, b_fc, out);
}

// round 10
// speedup vs baseline: 2.4242x; 1.1661x over previous
#include <cuda_runtime.h>

#define Bsz   128
#define Tt    512
#define INs   27
#define G4    1024
#define NB    128
#define OUTs  128

// ---- persistent device scratch (static: no runtime allocation) ----
__device__ float g_G[(size_t)Tt * G4 * Bsz];        // [t][g(1024)][b(128)]
// tagged-h ring: u64 = {h[2b+1] | h[2b]}, each fp32 carries step-tag in 2 LSBs.
// layout [slot(4)][grp(16)][k(256)][bpair(4)]
__device__ unsigned long long g_hx[4 * 16 * 256 * 4];

// ---------------- helpers ----------------
__device__ __forceinline__ void fma2(unsigned long long& d, unsigned long long a, unsigned long long b) {
    asm("fma.rn.f32x2 %0, %1, %2, %0;" : "+l"(d) : "l"(a), "l"(b));
}
__device__ __forceinline__ void add2(unsigned long long& d, unsigned long long a) {
    asm("add.rn.f32x2 %0, %0, %1;" : "+l"(d) : "l"(a));
}
__device__ __forceinline__ unsigned long long ldrx(const unsigned long long* p) {
    unsigned long long v;
    asm volatile("ld.relaxed.gpu.global.u64 %0, [%1];" : "=l"(v) : "l"(p) : "memory");
    return v;
}
__device__ __forceinline__ void strx(unsigned long long* p, unsigned long long v) {
    asm volatile("st.relaxed.gpu.global.u64 [%0], %1;" :: "l"(p), "l"(v) : "memory");
}
__device__ __forceinline__ float sigf(float x) {
    return __fdividef(1.f, 1.f + __expf(-x));
}
__device__ __forceinline__ float tanhf_(float x) {
    float e = __expf(-2.f * fabsf(x));
    float r = __fdividef(1.f - e, 1.f + e);
    return copysignf(r, x);
}

// ---------------- kernels ----------------
// G[t][g][b] = b_ih[g] + b_hh[g] + sum_{k<27} x[b][t][k] * W_ih[g][k]
// Also seed ring: slot 0 = h_0 = 0.0f (tag 0), slots 1..3 = tag-3 sentinel.
__global__ void pre_kernel(const float* __restrict__ x,
                           const float* __restrict__ W_ih,
                           const float* __restrict__ b_ih,
                           const float* __restrict__ b_hh) {
    __shared__ float xs[Bsz * INs];
    const int t   = blockIdx.x;
    const int gc  = blockIdx.y;       // 0..7, 128 gates each
    const int tid = threadIdx.x;      // = b  (blockDim.x == 128)

    if (gc == 0) {                    // 512*128 threads cover 65536 ring entries
        int e = t * 128 + tid;
        g_hx[e] = (e < 16384) ? 0ULL : 0x0000000300000003ULL;
    }

    for (int i = tid; i < Bsz * INs; i += 128) {
        int b = i / INs, k = i - b * INs;
        xs[i] = x[((size_t)b * Tt + t) * INs + k];
    }
    __syncthreads();
    float xr[INs];
    #pragma unroll
    for (int k = 0; k < INs; ++k) xr[k] = xs[tid * INs + k];

    for (int g0 = 0; g0 < 128; ++g0) {
        int g = (gc << 7) + g0;
        float acc = b_ih[g] + b_hh[g];
        const float* wr = W_ih + g * 47;   // NN_IN = 47, only first 27 cols used
        #pragma unroll
        for (int k = 0; k < INs; ++k) acc += xr[k] * __ldg(wr + k);
        g_G[((size_t)t * G4 + g) * Bsz + tid] = acc;
    }
}

// Persistent sequential LSTM. 128 blocks = 16 batch-groups(8 batches) x 8 j-tiles(32 j).
// Warp = k-split ks(0..15), 16 k each; lane = j-local; thread = all 4 gates of its j.
// Each warp's h slice comes from exactly ONE producer block and lives in a warp-private
// smem region (syncwarp only). One block sync per step (k-split reduce).
__global__ void __launch_bounds__(512, 1)
step_kernel(const float* __restrict__ W_hh,
            const float* __restrict__ W_fc,
            const float* __restrict__ b_fc,
            float* __restrict__ out) {
    extern __shared__ unsigned long long smu[];
    unsigned long long* sHd = smu;              // 1024 u64: [ks(16)][kl*4+bp]
    unsigned long long* sRd = smu + 1024;       // 2 bufs x 8192 u64: [ks][q][bp][j]
    unsigned long long* sG  = smu + 1024 + 16384;  // 512 u64: [epi tid(128)][q(4)]

    const int tid  = threadIdx.x;
    const int ks   = tid >> 5;                  // warp = k-split 0..15
    const int lane = tid & 31;                  // j-local
    const int grp  = blockIdx.x >> 3;           // batch-group 0..15
    const int jt   = blockIdx.x & 7;            // j-tile 0..7
    const int b0   = grp << 3;
    const int j0   = jt << 5;

    // ---- W slice: 4 gate-rows x 16 k in registers for the whole kernel ----
    float w[4][16];
    #pragma unroll
    for (int q = 0; q < 4; ++q) {
        const float* wp = W_hh + (((q << 8) + j0 + lane) << 8) + (ks << 4);
        #pragma unroll
        for (int kk = 0; kk < 16; ++kk) w[q][kk] = wp[kk];
    }

    // epilogue mapping (first 128 threads): warp = bpair, lane = j-local
    const bool epi = (tid < 128);
    const int ej = tid & 31;                    // j-local
    const int eb = tid >> 5;                    // bpair 0..3
    unsigned sGa = 0;
    if (epi) {
        unsigned sbase;
        asm("{ .reg .u64 t; cvta.to.shared.u64 t, %1; cvt.u32.u64 %0, t; }"
            : "=r"(sbase) : "l"(sG));
        sGa = sbase + (tid << 5);               // 4 u64 = 32 B per epi thread
    }

    float c0 = 0.f, c1 = 0.f;                   // cell state in registers

    for (int s = 0; s < Tt; ++s) {
        // ---- issue G prefetch via cp.async (epi threads) ----
        if (epi) {
            #pragma unroll
            for (int q = 0; q < 4; ++q) {
                const float* gs = g_G + ((((size_t)s << 10) + (q << 8) + j0 + ej) << 7)
                                      + b0 + (eb << 1);
                asm volatile("cp.async.ca.shared.global [%0], [%1], 8;"
                             :: "r"(sGa + (q << 3)), "l"(gs) : "memory");
            }
            asm volatile("cp.async.commit_group;" ::: "memory");
        }

        // ---- poll own h slice (2 u64/thread), warp-private staging ----
        {
            const unsigned long long* p0 =
                g_hx + (((size_t)(s & 3)) << 14) + ((size_t)grp << 10) + (ks << 6) + lane;
            const unsigned long long pat =
                (unsigned long long)((unsigned)(s >> 2) & 3u) * 0x0000000100000001ULL;
            unsigned long long v0 = ldrx(p0), v1 = ldrx(p0 + 32);
            int spins = 0;
            while (((v0 & 0x0000000300000003ULL) != pat) ||
                   ((v1 & 0x0000000300000003ULL) != pat)) {
                if (++spins > 2) __nanosleep(40);
                if ((v0 & 0x0000000300000003ULL) != pat) v0 = ldrx(p0);
                if ((v1 & 0x0000000300000003ULL) != pat) v1 = ldrx(p0 + 32);
            }
            sHd[(ks << 6) + lane]      = v0;
            sHd[(ks << 6) + lane + 32] = v1;
        }
        __syncwarp();

        // ---- GEMM: 4 gate-rows x 4 bpairs x 16 k; h broadcast LDS, W in regs ----
        unsigned long long acc[4][4];
        #pragma unroll
        for (int q = 0; q < 4; ++q)
            #pragma unroll
            for (int p = 0; p < 4; ++p) acc[q][p] = 0ULL;

        #pragma unroll
        for (int kk = 0; kk < 16; ++kk) {
            const ulonglong2* hh = (const ulonglong2*)(sHd + (ks << 6) + (kk << 2));
            ulonglong2 hA = hh[0];              // bpairs 0,1 (broadcast)
            ulonglong2 hB = hh[1];              // bpairs 2,3
            #pragma unroll
            for (int q = 0; q < 4; ++q) {
                unsigned long long wd;
                asm("mov.b64 %0, {%1, %1};" : "=l"(wd) : "f"(w[q][kk]));
                fma2(acc[q][0], hA.x, wd); fma2(acc[q][1], hA.y, wd);
                fma2(acc[q][2], hB.x, wd); fma2(acc[q][3], hB.y, wd);
            }
        }

        // ---- partials: sR[buf][ks][q][bp][j(32)] ----
        {
            unsigned long long* sRb = sRd + ((s & 1) << 13);
            #pragma unroll
            for (int q = 0; q < 4; ++q)
                #pragma unroll
                for (int p = 0; p < 4; ++p)
                    sRb[(((ks << 2) + q) << 7) + (p << 5) + lane] = acc[q][p];
        }
        __syncthreads();                        // the only block sync per step

        // ---- epilogue: sum 16 k-splits per gate, add G, LSTM, publish ----
        if (epi) {
            asm volatile("cp.async.wait_group 0;" ::: "memory");
            const unsigned long long* sRb = sRd + ((s & 1) << 13);
            unsigned long long vi = sG[(tid << 2) + 0];
            unsigned long long vf = sG[(tid << 2) + 1];
            unsigned long long vg = sG[(tid << 2) + 2];
            unsigned long long vo = sG[(tid << 2) + 3];
            const unsigned long long* rr = sRb + (eb << 5) + ej;
            #pragma unroll
            for (int k2 = 0; k2 < 16; ++k2) {
                add2(vi, rr[0]);
                add2(vf, rr[128]);
                add2(vg, rr[256]);
                add2(vo, rr[384]);
                rr += 512;
            }
            float iL, iH, fL, fH, gL, gH, oL, oH;
            asm("mov.b64 {%0, %1}, %2;" : "=f"(iL), "=f"(iH) : "l"(vi));
            asm("mov.b64 {%0, %1}, %2;" : "=f"(fL), "=f"(fH) : "l"(vf));
            asm("mov.b64 {%0, %1}, %2;" : "=f"(gL), "=f"(gH) : "l"(vg));
            asm("mov.b64 {%0, %1}, %2;" : "=f"(oL), "=f"(oH) : "l"(vo));
            c0 = sigf(fL) * c0 + sigf(iL) * tanhf_(gL);
            c1 = sigf(fH) * c1 + sigf(iH) * tanhf_(gH);
            float h0 = sigf(oL) * tanhf_(c0);
            float h1 = sigf(oH) * tanhf_(c1);
            unsigned tagv = ((unsigned)(s + 1) >> 2) & 3u;
            unsigned u0 = (__float_as_uint(h0) & ~3u) | tagv;
            unsigned u1 = (__float_as_uint(h1) & ~3u) | tagv;
            unsigned long long pkt = (unsigned long long)u0 | ((unsigned long long)u1 << 32);
            strx(g_hx + (((size_t)((s + 1) & 3)) << 14) + ((size_t)grp << 10)
                      + ((j0 + ej) << 2) + eb, pkt);
        }
        // no trailing sync: sR buffer parity protects the reduce; polls gate staging
    }

    // ---- classifier head: poll h_T (slot 0, tag 0) for this block's batch ----
    {
        float* sHf = (float*)smu;
        const int bb = blockIdx.x;               // batch = block id
        if (tid < 256) {
            const unsigned long long* p =
                g_hx + (((size_t)(bb >> 3)) << 10) + (tid << 2) + ((bb & 7) >> 1);
            const unsigned sh = (bb & 1) << 5;
            unsigned long long v = ldrx(p);
            while ((unsigned)((v >> sh) & 3ULL) != 0u) { __nanosleep(40); v = ldrx(p); }
            sHf[tid] = __uint_as_float((unsigned)(v >> sh));
        }
        __syncthreads();
        if (tid < OUTs) {
            float acc = b_fc[tid];
            const float* wr = W_fc + tid * 256;
            #pragma unroll 8
            for (int k = 0; k < 256; ++k)
                acc += sHf[k] * wr[k];
            out[bb * OUTs + tid] = acc;
        }
    }
}

// ---------------- launcher ----------------
extern "C" void kernel_launch(void* const* d_in, const int* in_sizes, int n_in,
                              void* d_out, int out_size) {
    const float* x    = (const float*)d_in[0];
    // d_in[1] = input_lengths (unused by the reference)
    const float* W_ih = (const float*)d_in[2];
    const float* W_hh = (const float*)d_in[3];
    const float* b_ih = (const float*)d_in[4];
    const float* b_hh = (const float*)d_in[5];
    // d_in[6], d_in[7] = W_xi, b_xi — dead code (memory never affects output)
    const float* W_fc = (const float*)d_in[8];
    const float* b_fc = (const float*)d_in[9];
    float* out = (float*)d_out;

    // smem: 8KB (sHd) + 128KB (sRd double buffer) + 4KB (sG) = 143360 bytes
    cudaFuncSetAttribute(step_kernel, cudaFuncAttributeMaxDynamicSharedMemorySize, 143360);

    pre_kernel<<<dim3(Tt, 8), 128>>>(x, W_ih, b_ih, b_hh);
    step_kernel<<<NB, 512, 143360>>>(W_hh, W_fc, b_fc, out);
}